// round 13
// baseline (speedup 1.0000x reference)
#include <cuda_runtime.h>
#include <cuda_fp16.h>
#include <cuda_fp8.h>

#define MAXN 50000
#define MAXE 1600000

// ---------------- scratch (static device allocations) ----------------
__device__ int   g_is64;
__device__ int   g_cnt[MAXN];
__device__ int   g_rowptr[MAXN + 1];
__device__ int   g_cursor[MAXN];
__device__ int   g_part[128];
__device__ int   g_adj[MAXE + MAXN];
__device__ __align__(16) unsigned char g_h1f8[MAXN * 64];  // layer-1 features, fp8 e4m3
__device__ __align__(16) unsigned char g_h2f8[MAXN * 32];  // layer-2 features, fp8 e4m3
__device__ float g_al1s[MAXN * 8], g_al1d[MAXN * 8];
__device__ float g_al2s[MAXN * 8], g_al2d[MAXN * 8];
__device__ float g_Mf[16 * 32];
__device__ float g_cf[16];

// fp8x2 helpers
__device__ __forceinline__ unsigned short f2_to_fp8x2(float a, float b) {
    return (unsigned short)__nv_cvt_float2_to_fp8x2(make_float2(a, b), __NV_SATFINITE, __NV_E4M3);
}
__device__ __forceinline__ float2 fp8x2_to_f2(unsigned short v) {
    __half2_raw h = __nv_cvt_fp8x2_to_halfraw2((__nv_fp8x2_storage_t)v, __NV_E4M3);
    return __half22float2(*reinterpret_cast<__half2*>(&h));
}

// read edge value i (src row: i in [0,E); dst row: i in [E,2E))
__device__ __forceinline__ int edge_val(const void* ei, long long idx) {
    return g_is64 ? (int)((const long long*)ei)[idx] : ((const int*)ei)[idx];
}

// ---------------- dtype probe + CSR build ----------------
__global__ void k_zero(const unsigned long long* __restrict__ w, int N, int E) {
    int i = blockIdx.x * blockDim.x + threadIdx.x;
    if (i < N) g_cnt[i] = 0;
    if (i == 0) g_is64 = 1;  // optimistic; cleared below if int32
    int n = E < 2048 ? E : 2048;
    if (i < n && (w[i] >> 32) != 0ull) g_is64 = 0;  // high half set => int32 pairs
}

__global__ void k_count(const void* __restrict__ ei, int E) {
    int i = blockIdx.x * blockDim.x + threadIdx.x;
    if (i < E) {
        int d = edge_val(ei, (long long)E + i);
        atomicAdd(&g_cnt[d], 1);
    }
}

__global__ void k_blocksum(int N) {
    __shared__ int sh[1024];
    int i = blockIdx.x * 1024 + threadIdx.x;
    sh[threadIdx.x] = (i < N) ? (g_cnt[i] + 1) : 0;  // +1 = self loop
    __syncthreads();
    for (int o = 512; o > 0; o >>= 1) {
        if (threadIdx.x < o) sh[threadIdx.x] += sh[threadIdx.x + o];
        __syncthreads();
    }
    if (threadIdx.x == 0) g_part[blockIdx.x] = sh[0];
}

// block-level inclusive scan; block offset = sum of preceding blocks' partials
__global__ void k_scan(int N, int nb) {
    __shared__ int sh[1024];
    __shared__ int spart[64];
    __shared__ int soff;
    int tid = threadIdx.x;
    if (tid < 64) spart[tid] = (tid < (int)blockIdx.x && tid < nb) ? g_part[tid] : 0;
    __syncthreads();
    if (tid < 32) {
        int v = spart[tid] + spart[tid + 32];
#pragma unroll
        for (int o = 16; o > 0; o >>= 1) v += __shfl_xor_sync(0xffffffffu, v, o);
        if (tid == 0) soff = v;
    }
    int i = blockIdx.x * 1024 + tid;
    int v = (i < N) ? (g_cnt[i] + 1) : 0;
    sh[tid] = v;
    __syncthreads();
    for (int o = 1; o < 1024; o <<= 1) {
        int t = 0;
        if (tid >= (unsigned)o) t = sh[tid - o];
        __syncthreads();
        sh[tid] += t;
        __syncthreads();
    }
    if (i < N) {
        int incl = sh[tid] + soff;
        g_rowptr[i + 1] = incl;
        g_cursor[i] = incl - v;
        if (i == 0) g_rowptr[0] = 0;
    }
}

__global__ void k_scatter(const void* __restrict__ ei, int E, int N) {
    int i = blockIdx.x * blockDim.x + threadIdx.x;
    if (i < E) {
        int d = edge_val(ei, (long long)E + i);
        int s = edge_val(ei, i);
        int pos = atomicAdd(&g_cursor[d], 1);
        g_adj[pos] = s;
    } else if (i < E + N) {  // self loops
        int n = i - E;
        int pos = atomicAdd(&g_cursor[n], 1);
        g_adj[pos] = n;
    }
}

// ------ GEMM layer 1: 4 channels x 4 nodes register tile ------
// Fused: fp8 feature-table pack + attention logits.
__global__ __launch_bounds__(256) void k_gemm1(const float* __restrict__ X,
                                               const float* __restrict__ W,
                                               const float* __restrict__ a_src,
                                               const float* __restrict__ a_dst, int N) {
    constexpr int FIN = 128, TX = 16, NN = 4, NPB = 64;
    __shared__ float4 Ws4[FIN * TX];  // W as [FIN][TX] float4
    int tid = threadIdx.x;
    int tx = tid % TX, ty = tid / TX;
    const float4* W4 = reinterpret_cast<const float4*>(W);
    for (int idx = tid; idx < FIN * TX; idx += 256) Ws4[idx] = W4[idx];
    float4 as4 = __ldg(reinterpret_cast<const float4*>(a_src) + tx);
    float4 ad4 = __ldg(reinterpret_cast<const float4*>(a_dst) + tx);
    __syncthreads();

    const float4* X4 = reinterpret_cast<const float4*>(X);
    int n0 = blockIdx.x * NPB + ty * NN;
    bool v[NN];
#pragma unroll
    for (int nn = 0; nn < NN; nn++) v[nn] = (n0 + nn) < N;

    float acc[NN][4];
#pragma unroll
    for (int nn = 0; nn < NN; nn++)
        acc[nn][0] = acc[nn][1] = acc[nn][2] = acc[nn][3] = 0.f;

#pragma unroll 2
    for (int kq = 0; kq < FIN / 4; kq++) {
        float4 w0 = Ws4[(4 * kq + 0) * TX + tx];
        float4 w1 = Ws4[(4 * kq + 1) * TX + tx];
        float4 w2 = Ws4[(4 * kq + 2) * TX + tx];
        float4 w3 = Ws4[(4 * kq + 3) * TX + tx];
#pragma unroll
        for (int nn = 0; nn < NN; nn++) {
            float4 xv = v[nn] ? __ldg(&X4[(n0 + nn) * (FIN / 4) + kq])
                              : make_float4(0.f, 0.f, 0.f, 0.f);
            acc[nn][0] = fmaf(xv.x, w0.x, acc[nn][0]);
            acc[nn][1] = fmaf(xv.x, w0.y, acc[nn][1]);
            acc[nn][2] = fmaf(xv.x, w0.z, acc[nn][2]);
            acc[nn][3] = fmaf(xv.x, w0.w, acc[nn][3]);
            acc[nn][0] = fmaf(xv.y, w1.x, acc[nn][0]);
            acc[nn][1] = fmaf(xv.y, w1.y, acc[nn][1]);
            acc[nn][2] = fmaf(xv.y, w1.z, acc[nn][2]);
            acc[nn][3] = fmaf(xv.y, w1.w, acc[nn][3]);
            acc[nn][0] = fmaf(xv.z, w2.x, acc[nn][0]);
            acc[nn][1] = fmaf(xv.z, w2.y, acc[nn][1]);
            acc[nn][2] = fmaf(xv.z, w2.z, acc[nn][2]);
            acc[nn][3] = fmaf(xv.z, w2.w, acc[nn][3]);
            acc[nn][0] = fmaf(xv.w, w3.x, acc[nn][0]);
            acc[nn][1] = fmaf(xv.w, w3.y, acc[nn][1]);
            acc[nn][2] = fmaf(xv.w, w3.z, acc[nn][2]);
            acc[nn][3] = fmaf(xv.w, w3.w, acc[nn][3]);
        }
    }

#pragma unroll
    for (int nn = 0; nn < NN; nn++) {
        int n = n0 + nn;
        if (v[nn]) {  // fp8 pack: this thread's 4 contiguous channels
            unsigned int p = (unsigned int)f2_to_fp8x2(acc[nn][0], acc[nn][1]) |
                             ((unsigned int)f2_to_fp8x2(acc[nn][2], acc[nn][3]) << 16);
            *reinterpret_cast<unsigned int*>(&g_h1f8[n * 64 + 4 * tx]) = p;
        }
        float ps = acc[nn][0] * as4.x + acc[nn][1] * as4.y +
                   acc[nn][2] * as4.z + acc[nn][3] * as4.w;
        float pd = acc[nn][0] * ad4.x + acc[nn][1] * ad4.y +
                   acc[nn][2] * ad4.z + acc[nn][3] * ad4.w;
        ps += __shfl_xor_sync(0xffffffffu, ps, 1);
        pd += __shfl_xor_sync(0xffffffffu, pd, 1);
        if (v[nn] && (tx & 1) == 0) {
            int head = tx >> 1;
            g_al1s[n * 8 + head] = ps;
            g_al1d[n * 8 + head] = pd;
        }
    }
}

// ------ agg layer 1: 16 lanes/node, cooperative adj prefetch; FUSED gemm2+logits2 ------
// Per 16-edge block: one coalesced adj load, indices distributed via shfl.
// Per edge: als + fp8 feature gathers only (no dependent adj load in the chain).
__global__ __launch_bounds__(256) void k_agg1(const float* __restrict__ b1,
                                              const float* __restrict__ W2,
                                              const float* __restrict__ a2s,
                                              const float* __restrict__ a2d, int N) {
    __shared__ float W2s[64 * 32];     // 8KB, [k][j] row-major
    __shared__ float smh1[16][64];     // 4KB, staged h1 per node slot
    __shared__ float a2sS[32], a2dS[32];
    int tid = threadIdx.x;
    for (int idx = tid; idx < 64 * 32; idx += 256) W2s[idx] = W2[idx];
    if (tid < 32) { a2sS[tid] = a2s[tid]; a2dS[tid] = a2d[tid]; }
    __syncthreads();

    int warp = tid >> 5;
    int lane = tid & 31;
    int sub = lane >> 4, gl = lane & 15;
    int slot = warp * 2 + sub;
    int node = blockIdx.x * 16 + slot;
    bool valid = node < N;
    int base = 0, deg = 0;
    if (valid) { base = g_rowptr[node]; deg = g_rowptr[node + 1] - base; }
    int degmax = max(deg, __shfl_xor_sync(0xffffffffu, deg, 16));

    int hh = gl >> 1;  // head owning this lane's 4 channels (C=8)
    float adh = valid ? g_al1d[node * 8 + hh] : 0.f;

    float ax = 0.f, ay = 0.f, az = 0.f, aw = 0.f, denom = 0.f;
    int srcl = sub << 4;
    for (int jb = 0; jb < degmax; jb += 16) {
        int aval = (jb + gl < deg) ? __ldg(&g_adj[base + jb + gl]) : 0;
        int cnt = degmax - jb;  // warp-uniform
        if (cnt >= 16) {
#pragma unroll 4
            for (int jj = 0; jj < 16; jj++) {
                int sid = __shfl_sync(0xffffffffu, aval, srcl + jj);
                float a = __ldg(&g_al1s[sid * 8 + hh]) + adh;
                a = a > 0.f ? a : 0.2f * a;
                float w = (jb + jj < deg) ? __expf(a) : 0.f;
                denom += w;
                unsigned int u =
                    __ldg(reinterpret_cast<const unsigned int*>(&g_h1f8[sid * 64 + 4 * gl]));
                float2 f01 = fp8x2_to_f2((unsigned short)(u & 0xFFFFu));
                float2 f23 = fp8x2_to_f2((unsigned short)(u >> 16));
                ax = fmaf(f01.x, w, ax);
                ay = fmaf(f01.y, w, ay);
                az = fmaf(f23.x, w, az);
                aw = fmaf(f23.y, w, aw);
            }
        } else {
#pragma unroll 4
            for (int jj = 0; jj < cnt; jj++) {
                int sid = __shfl_sync(0xffffffffu, aval, srcl + jj);
                float a = __ldg(&g_al1s[sid * 8 + hh]) + adh;
                a = a > 0.f ? a : 0.2f * a;
                float w = (jb + jj < deg) ? __expf(a) : 0.f;
                denom += w;
                unsigned int u =
                    __ldg(reinterpret_cast<const unsigned int*>(&g_h1f8[sid * 64 + 4 * gl]));
                float2 f01 = fp8x2_to_f2((unsigned short)(u & 0xFFFFu));
                float2 f23 = fp8x2_to_f2((unsigned short)(u >> 16));
                ax = fmaf(f01.x, w, ax);
                ay = fmaf(f01.y, w, ay);
                az = fmaf(f23.x, w, az);
                aw = fmaf(f23.y, w, aw);
            }
        }
    }
    __syncwarp();
    float inv = 1.f / (denom + 1e-16f);
    float4 b4 = __ldg(reinterpret_cast<const float4*>(b1) + gl);
    float o0 = fmaf(ax, inv, b4.x);
    float o1 = fmaf(ay, inv, b4.y);
    float o2 = fmaf(az, inv, b4.z);
    float o3 = fmaf(aw, inv, b4.w);
    o0 = o0 > 0.f ? o0 : (expf(o0) - 1.f);  // elu
    o1 = o1 > 0.f ? o1 : (expf(o1) - 1.f);
    o2 = o2 > 0.f ? o2 : (expf(o2) - 1.f);
    o3 = o3 > 0.f ? o3 : (expf(o3) - 1.f);
    *reinterpret_cast<float4*>(&smh1[slot][4 * gl]) = make_float4(o0, o1, o2, o3);
    __syncwarp();

    // gemm2 for this node: lane computes h2 channels j0=2*gl, j0+1
    int j0 = 2 * gl;
    float c0 = 0.f, c1 = 0.f;
    const float4* hrow = reinterpret_cast<const float4*>(smh1[slot]);
#pragma unroll
    for (int kq = 0; kq < 16; kq++) {
        float4 h = hrow[kq];
        float2 w0 = *reinterpret_cast<const float2*>(&W2s[(4 * kq + 0) * 32 + j0]);
        float2 w1 = *reinterpret_cast<const float2*>(&W2s[(4 * kq + 1) * 32 + j0]);
        float2 w2 = *reinterpret_cast<const float2*>(&W2s[(4 * kq + 2) * 32 + j0]);
        float2 w3 = *reinterpret_cast<const float2*>(&W2s[(4 * kq + 3) * 32 + j0]);
        c0 = fmaf(h.x, w0.x, c0); c1 = fmaf(h.x, w0.y, c1);
        c0 = fmaf(h.y, w1.x, c0); c1 = fmaf(h.y, w1.y, c1);
        c0 = fmaf(h.z, w2.x, c0); c1 = fmaf(h.z, w2.y, c1);
        c0 = fmaf(h.w, w3.x, c0); c1 = fmaf(h.w, w3.y, c1);
    }
    if (valid)
        *reinterpret_cast<unsigned short*>(&g_h2f8[node * 32 + j0]) = f2_to_fp8x2(c0, c1);
    float ps = c0 * a2sS[j0] + c1 * a2sS[j0 + 1];
    float pd = c0 * a2dS[j0] + c1 * a2dS[j0 + 1];
    ps += __shfl_xor_sync(0xffffffffu, ps, 1);
    pd += __shfl_xor_sync(0xffffffffu, pd, 1);
    if (valid && (gl & 1) == 0) {
        int head = gl >> 1;
        g_al2s[node * 8 + head] = ps;
        g_al2d[node * 8 + head] = pd;
    }
}

// ---------------- fold MHA(v-path)+out_proj+fc into one 16x32 matrix ----------------
__global__ void k_prep(const float* __restrict__ in_w, const float* __restrict__ in_b,
                       const float* __restrict__ ow, const float* __restrict__ ob,
                       const float* __restrict__ fw, const float* __restrict__ fb) {
    __shared__ float T[32 * 32];
    __shared__ float u[32];
    int tid = threadIdx.x;  // 1024
    {
        int r = tid >> 5, j = tid & 31;
        float acc = 0.f;
        for (int p = 0; p < 32; p++) acc = fmaf(ow[r * 32 + p], in_w[(64 + p) * 32 + j], acc);
        T[r * 32 + j] = acc;
    }
    if (tid < 32) {
        float acc = ob[tid];
        for (int p = 0; p < 32; p++) acc = fmaf(ow[tid * 32 + p], in_b[64 + p], acc);
        u[tid] = acc;
    }
    __syncthreads();
    if (tid < 512) {
        int i = tid >> 5, j = tid & 31;
        float acc = 0.f;
        for (int r = 0; r < 32; r++) acc = fmaf(fw[i * 32 + r], T[r * 32 + j], acc);
        g_Mf[i * 32 + j] = acc;
    }
    if (tid < 16) {
        float acc = fb[tid];
        for (int r = 0; r < 32; r++) acc = fmaf(fw[tid * 32 + r], u[r], acc);
        g_cf[tid] = acc;
    }
}

// ------ agg layer 2: 8 lanes/node, cooperative adj prefetch; FUSED logits+softmax ------
__global__ __launch_bounds__(256) void k_agg2(const float* __restrict__ b2,
                                              float* __restrict__ out, int N) {
    __shared__ float MfT[32 * 16];   // 2KB, [k][i] (transposed g_Mf)
    __shared__ float cfs[16];
    __shared__ float smh2[32][32];   // 4KB
    int tid = threadIdx.x;  // 256
    for (int idx = tid; idx < 512; idx += 256) {
        int k = idx >> 4, i = idx & 15;
        MfT[idx] = g_Mf[i * 32 + k];
    }
    if (tid < 16) cfs[tid] = g_cf[tid];
    __syncthreads();

    int warp = tid >> 5;
    int lane = tid & 31;
    int sub = lane >> 3, gl = lane & 7;
    int slot = warp * 4 + sub;
    int node = blockIdx.x * 32 + slot;
    bool valid = node < N;
    int base = 0, deg = 0;
    if (valid) { base = g_rowptr[node]; deg = g_rowptr[node + 1] - base; }
    int degmax = max(deg, __shfl_xor_sync(0xffffffffu, deg, 8));
    degmax = max(degmax, __shfl_xor_sync(0xffffffffu, degmax, 16));

    int hh = gl;  // C=4: head = gl
    float adh = valid ? g_al2d[node * 8 + hh] : 0.f;

    float ax = 0.f, ay = 0.f, az = 0.f, aw = 0.f, denom = 0.f;
    int srcl = sub << 3;
    for (int jb = 0; jb < degmax; jb += 8) {
        int aval = (jb + gl < deg) ? __ldg(&g_adj[base + jb + gl]) : 0;
        int cnt = degmax - jb;  // warp-uniform
        if (cnt >= 8) {
#pragma unroll 4
            for (int jj = 0; jj < 8; jj++) {
                int sid = __shfl_sync(0xffffffffu, aval, srcl + jj);
                float a = __ldg(&g_al2s[sid * 8 + hh]) + adh;
                a = a > 0.f ? a : 0.2f * a;
                float w = (jb + jj < deg) ? __expf(a) : 0.f;
                denom += w;
                unsigned int u =
                    __ldg(reinterpret_cast<const unsigned int*>(&g_h2f8[sid * 32 + 4 * gl]));
                float2 f01 = fp8x2_to_f2((unsigned short)(u & 0xFFFFu));
                float2 f23 = fp8x2_to_f2((unsigned short)(u >> 16));
                ax = fmaf(f01.x, w, ax);
                ay = fmaf(f01.y, w, ay);
                az = fmaf(f23.x, w, az);
                aw = fmaf(f23.y, w, aw);
            }
        } else {
#pragma unroll 4
            for (int jj = 0; jj < cnt; jj++) {
                int sid = __shfl_sync(0xffffffffu, aval, srcl + jj);
                float a = __ldg(&g_al2s[sid * 8 + hh]) + adh;
                a = a > 0.f ? a : 0.2f * a;
                float w = (jb + jj < deg) ? __expf(a) : 0.f;
                denom += w;
                unsigned int u =
                    __ldg(reinterpret_cast<const unsigned int*>(&g_h2f8[sid * 32 + 4 * gl]));
                float2 f01 = fp8x2_to_f2((unsigned short)(u & 0xFFFFu));
                float2 f23 = fp8x2_to_f2((unsigned short)(u >> 16));
                ax = fmaf(f01.x, w, ax);
                ay = fmaf(f01.y, w, ay);
                az = fmaf(f23.x, w, az);
                aw = fmaf(f23.y, w, aw);
            }
        }
    }
    __syncwarp();
    float inv = 1.f / (denom + 1e-16f);
    float4 b4 = __ldg(reinterpret_cast<const float4*>(b2) + gl);
    float o0 = fmaf(ax, inv, b4.x);
    float o1 = fmaf(ay, inv, b4.y);
    float o2 = fmaf(az, inv, b4.z);
    float o3 = fmaf(aw, inv, b4.w);
    o0 = o0 > 0.f ? o0 : (expf(o0) - 1.f);  // elu
    o1 = o1 > 0.f ? o1 : (expf(o1) - 1.f);
    o2 = o2 > 0.f ? o2 : (expf(o2) - 1.f);
    o3 = o3 > 0.f ? o3 : (expf(o3) - 1.f);
    *reinterpret_cast<float4*>(&smh2[slot][4 * gl]) = make_float4(o0, o1, o2, o3);
    __syncwarp();

    // logits i0=2*gl, i0+1
    int i0 = 2 * gl;
    float l0 = cfs[i0], l1 = cfs[i0 + 1];
    const float4* hrow = reinterpret_cast<const float4*>(smh2[slot]);
#pragma unroll
    for (int kq = 0; kq < 8; kq++) {
        float4 h = hrow[kq];
        float2 m0 = *reinterpret_cast<const float2*>(&MfT[(4 * kq + 0) * 16 + i0]);
        float2 m1 = *reinterpret_cast<const float2*>(&MfT[(4 * kq + 1) * 16 + i0]);
        float2 m2 = *reinterpret_cast<const float2*>(&MfT[(4 * kq + 2) * 16 + i0]);
        float2 m3 = *reinterpret_cast<const float2*>(&MfT[(4 * kq + 3) * 16 + i0]);
        l0 = fmaf(h.x, m0.x, l0); l1 = fmaf(h.x, m0.y, l1);
        l0 = fmaf(h.y, m1.x, l0); l1 = fmaf(h.y, m1.y, l1);
        l0 = fmaf(h.z, m2.x, l0); l1 = fmaf(h.z, m2.y, l1);
        l0 = fmaf(h.w, m3.x, l0); l1 = fmaf(h.w, m3.y, l1);
    }
    float m = fmaxf(l0, l1);
#pragma unroll
    for (int o = 1; o < 8; o <<= 1) m = fmaxf(m, __shfl_xor_sync(0xffffffffu, m, o));
    float se = expf(l0 - m) + expf(l1 - m);
#pragma unroll
    for (int o = 1; o < 8; o <<= 1) se += __shfl_xor_sync(0xffffffffu, se, o);
    float lse = m + logf(se);
    if (valid)
        *reinterpret_cast<float2*>(&out[node * 16 + i0]) = make_float2(l0 - lse, l1 - lse);
}

// ---------------- launcher: forked graph (CSR chain || gemm1+prep) ----------------
extern "C" void kernel_launch(void* const* d_in, const int* in_sizes, int n_in,
                              void* d_out, int out_size) {
    const float* x = (const float*)d_in[0];
    const void* ei = d_in[1];
    const float* W1 = (const float*)d_in[2];
    const float* a1s = (const float*)d_in[3];
    const float* a1d = (const float*)d_in[4];
    const float* b1 = (const float*)d_in[5];
    const float* W2 = (const float*)d_in[6];
    const float* a2s = (const float*)d_in[7];
    const float* a2d = (const float*)d_in[8];
    const float* b2 = (const float*)d_in[9];
    const float* ipw = (const float*)d_in[10];
    const float* ipb = (const float*)d_in[11];
    const float* opw = (const float*)d_in[12];
    const float* opb = (const float*)d_in[13];
    const float* fw = (const float*)d_in[14];
    const float* fb = (const float*)d_in[15];

    int N = in_sizes[0] / 128;
    int E = in_sizes[1] / 2;
    int nb = (N + 1023) / 1024;

    cudaStream_t s2;
    cudaStreamCreateWithFlags(&s2, cudaStreamNonBlocking);
    cudaEvent_t e0, e1;
    cudaEventCreateWithFlags(&e0, cudaEventDisableTiming);
    cudaEventCreateWithFlags(&e1, cudaEventDisableTiming);

    // fork: side branch runs gemm1 + prep (independent of edge data)
    cudaEventRecord(e0, 0);
    cudaStreamWaitEvent(s2, e0, 0);
    k_gemm1<<<(N + 63) / 64, 256, 0, s2>>>(x, W1, a1s, a1d, N);
    k_prep<<<1, 1024, 0, s2>>>(ipw, ipb, opw, opb, fw, fb);
    cudaEventRecord(e1, s2);

    // main branch: CSR build by dst
    k_zero<<<(N + 255) / 256, 256>>>((const unsigned long long*)ei, N, E);
    k_count<<<(E + 255) / 256, 256>>>(ei, E);
    k_blocksum<<<nb, 1024>>>(N);
    k_scan<<<nb, 1024>>>(N, nb);
    k_scatter<<<(E + N + 255) / 256, 256>>>(ei, E, N);

    // join, then the two fused aggregation layers
    cudaStreamWaitEvent(0, e1, 0);
    k_agg1<<<(N + 15) / 16, 256>>>(b1, W2, a2s, a2d, N);
    k_agg2<<<(N + 31) / 32, 256>>>(b2, (float*)d_out, N);

    cudaStreamDestroy(s2);
    cudaEventDestroy(e0);
    cudaEventDestroy(e1);
}

// round 14
// speedup vs baseline: 1.1339x; 1.1339x over previous
#include <cuda_runtime.h>
#include <cuda_fp16.h>
#include <cuda_fp8.h>

#define MAXN 50000
#define MAXE 1600000

// ---------------- scratch (static device allocations) ----------------
__device__ int   g_is64;
__device__ int   g_cnt[MAXN];
__device__ int   g_rowptr[MAXN + 1];
__device__ int   g_cursor[MAXN];
__device__ int   g_part[128];
__device__ int   g_adj[MAXE + MAXN];
__device__ __align__(16) unsigned char g_h1f8[MAXN * 64];  // layer-1 features, fp8 e4m3
__device__ __align__(16) unsigned char g_h2f8[MAXN * 32];  // layer-2 features, fp8 e4m3
__device__ float g_al1s[MAXN * 8], g_al1d[MAXN * 8];
__device__ float g_al2s[MAXN * 8], g_al2d[MAXN * 8];
__device__ float g_Mf[16 * 32];
__device__ float g_cf[16];

// fp8x2 helpers
__device__ __forceinline__ unsigned short f2_to_fp8x2(float a, float b) {
    return (unsigned short)__nv_cvt_float2_to_fp8x2(make_float2(a, b), __NV_SATFINITE, __NV_E4M3);
}
__device__ __forceinline__ float2 fp8x2_to_f2(unsigned short v) {
    __half2_raw h = __nv_cvt_fp8x2_to_halfraw2((__nv_fp8x2_storage_t)v, __NV_E4M3);
    return __half22float2(*reinterpret_cast<__half2*>(&h));
}

// read edge value i (src row: i in [0,E); dst row: i in [E,2E))
__device__ __forceinline__ int edge_val(const void* ei, long long idx) {
    return g_is64 ? (int)((const long long*)ei)[idx] : ((const int*)ei)[idx];
}

// ---------------- dtype probe + CSR build ----------------
__global__ void k_zero(const unsigned long long* __restrict__ w, int N, int E) {
    int i = blockIdx.x * blockDim.x + threadIdx.x;
    if (i < N) g_cnt[i] = 0;
    if (i == 0) g_is64 = 1;  // optimistic; cleared below if int32
    int n = E < 2048 ? E : 2048;
    if (i < n && (w[i] >> 32) != 0ull) g_is64 = 0;  // high half set => int32 pairs
}

__global__ void k_count(const void* __restrict__ ei, int E) {
    int i = blockIdx.x * blockDim.x + threadIdx.x;
    if (i < E) {
        int d = edge_val(ei, (long long)E + i);
        atomicAdd(&g_cnt[d], 1);
    }
}

__global__ void k_blocksum(int N) {
    __shared__ int sh[1024];
    int i = blockIdx.x * 1024 + threadIdx.x;
    sh[threadIdx.x] = (i < N) ? (g_cnt[i] + 1) : 0;  // +1 = self loop
    __syncthreads();
    for (int o = 512; o > 0; o >>= 1) {
        if (threadIdx.x < o) sh[threadIdx.x] += sh[threadIdx.x + o];
        __syncthreads();
    }
    if (threadIdx.x == 0) g_part[blockIdx.x] = sh[0];
}

// block-level inclusive scan; block offset = sum of preceding blocks' partials
__global__ void k_scan(int N, int nb) {
    __shared__ int sh[1024];
    __shared__ int spart[64];
    __shared__ int soff;
    int tid = threadIdx.x;
    if (tid < 64) spart[tid] = (tid < (int)blockIdx.x && tid < nb) ? g_part[tid] : 0;
    __syncthreads();
    if (tid < 32) {
        int v = spart[tid] + spart[tid + 32];
#pragma unroll
        for (int o = 16; o > 0; o >>= 1) v += __shfl_xor_sync(0xffffffffu, v, o);
        if (tid == 0) soff = v;
    }
    int i = blockIdx.x * 1024 + tid;
    int v = (i < N) ? (g_cnt[i] + 1) : 0;
    sh[tid] = v;
    __syncthreads();
    for (int o = 1; o < 1024; o <<= 1) {
        int t = 0;
        if (tid >= (unsigned)o) t = sh[tid - o];
        __syncthreads();
        sh[tid] += t;
        __syncthreads();
    }
    if (i < N) {
        int incl = sh[tid] + soff;
        g_rowptr[i + 1] = incl;
        g_cursor[i] = incl - v;
        if (i == 0) g_rowptr[0] = 0;
    }
}

__global__ void k_scatter(const void* __restrict__ ei, int E, int N) {
    int i = blockIdx.x * blockDim.x + threadIdx.x;
    if (i < E) {
        int d = edge_val(ei, (long long)E + i);
        int s = edge_val(ei, i);
        int pos = atomicAdd(&g_cursor[d], 1);
        g_adj[pos] = s;
    } else if (i < E + N) {  // self loops
        int n = i - E;
        int pos = atomicAdd(&g_cursor[n], 1);
        g_adj[pos] = n;
    }
}

// ------ GEMM layer 1: 4 channels x 4 nodes register tile ------
// Fused: fp8 feature-table pack + attention logits.
__global__ __launch_bounds__(256) void k_gemm1(const float* __restrict__ X,
                                               const float* __restrict__ W,
                                               const float* __restrict__ a_src,
                                               const float* __restrict__ a_dst, int N) {
    constexpr int FIN = 128, TX = 16, NN = 4, NPB = 64;
    __shared__ float4 Ws4[FIN * TX];  // W as [FIN][TX] float4
    int tid = threadIdx.x;
    int tx = tid % TX, ty = tid / TX;
    const float4* W4 = reinterpret_cast<const float4*>(W);
    for (int idx = tid; idx < FIN * TX; idx += 256) Ws4[idx] = W4[idx];
    float4 as4 = __ldg(reinterpret_cast<const float4*>(a_src) + tx);
    float4 ad4 = __ldg(reinterpret_cast<const float4*>(a_dst) + tx);
    __syncthreads();

    const float4* X4 = reinterpret_cast<const float4*>(X);
    int n0 = blockIdx.x * NPB + ty * NN;
    bool v[NN];
#pragma unroll
    for (int nn = 0; nn < NN; nn++) v[nn] = (n0 + nn) < N;

    float acc[NN][4];
#pragma unroll
    for (int nn = 0; nn < NN; nn++)
        acc[nn][0] = acc[nn][1] = acc[nn][2] = acc[nn][3] = 0.f;

#pragma unroll 2
    for (int kq = 0; kq < FIN / 4; kq++) {
        float4 w0 = Ws4[(4 * kq + 0) * TX + tx];
        float4 w1 = Ws4[(4 * kq + 1) * TX + tx];
        float4 w2 = Ws4[(4 * kq + 2) * TX + tx];
        float4 w3 = Ws4[(4 * kq + 3) * TX + tx];
#pragma unroll
        for (int nn = 0; nn < NN; nn++) {
            float4 xv = v[nn] ? __ldg(&X4[(n0 + nn) * (FIN / 4) + kq])
                              : make_float4(0.f, 0.f, 0.f, 0.f);
            acc[nn][0] = fmaf(xv.x, w0.x, acc[nn][0]);
            acc[nn][1] = fmaf(xv.x, w0.y, acc[nn][1]);
            acc[nn][2] = fmaf(xv.x, w0.z, acc[nn][2]);
            acc[nn][3] = fmaf(xv.x, w0.w, acc[nn][3]);
            acc[nn][0] = fmaf(xv.y, w1.x, acc[nn][0]);
            acc[nn][1] = fmaf(xv.y, w1.y, acc[nn][1]);
            acc[nn][2] = fmaf(xv.y, w1.z, acc[nn][2]);
            acc[nn][3] = fmaf(xv.y, w1.w, acc[nn][3]);
            acc[nn][0] = fmaf(xv.z, w2.x, acc[nn][0]);
            acc[nn][1] = fmaf(xv.z, w2.y, acc[nn][1]);
            acc[nn][2] = fmaf(xv.z, w2.z, acc[nn][2]);
            acc[nn][3] = fmaf(xv.z, w2.w, acc[nn][3]);
            acc[nn][0] = fmaf(xv.w, w3.x, acc[nn][0]);
            acc[nn][1] = fmaf(xv.w, w3.y, acc[nn][1]);
            acc[nn][2] = fmaf(xv.w, w3.z, acc[nn][2]);
            acc[nn][3] = fmaf(xv.w, w3.w, acc[nn][3]);
        }
    }

#pragma unroll
    for (int nn = 0; nn < NN; nn++) {
        int n = n0 + nn;
        if (v[nn]) {  // fp8 pack: this thread's 4 contiguous channels
            unsigned int p = (unsigned int)f2_to_fp8x2(acc[nn][0], acc[nn][1]) |
                             ((unsigned int)f2_to_fp8x2(acc[nn][2], acc[nn][3]) << 16);
            *reinterpret_cast<unsigned int*>(&g_h1f8[n * 64 + 4 * tx]) = p;
        }
        float ps = acc[nn][0] * as4.x + acc[nn][1] * as4.y +
                   acc[nn][2] * as4.z + acc[nn][3] * as4.w;
        float pd = acc[nn][0] * ad4.x + acc[nn][1] * ad4.y +
                   acc[nn][2] * ad4.z + acc[nn][3] * ad4.w;
        ps += __shfl_xor_sync(0xffffffffu, ps, 1);
        pd += __shfl_xor_sync(0xffffffffu, pd, 1);
        if (v[nn] && (tx & 1) == 0) {
            int head = tx >> 1;
            g_al1s[n * 8 + head] = ps;
            g_al1d[n * 8 + head] = pd;
        }
    }
}

// ------ agg layer 1 (single-pass softmax, fp8 gathers) FUSED gemm2 + layer-2 logits ------
// 16 lanes per node; per lane 4 channels of h1 (fp8).
__global__ __launch_bounds__(256) void k_agg1(const float* __restrict__ b1,
                                              const float* __restrict__ W2,
                                              const float* __restrict__ a2s,
                                              const float* __restrict__ a2d, int N) {
    __shared__ float W2s[64 * 32];     // 8KB, [k][j] row-major
    __shared__ float smh1[16][64];     // 4KB, staged h1 per node slot
    __shared__ float a2sS[32], a2dS[32];
    int tid = threadIdx.x;
    for (int idx = tid; idx < 64 * 32; idx += 256) W2s[idx] = W2[idx];
    if (tid < 32) { a2sS[tid] = a2s[tid]; a2dS[tid] = a2d[tid]; }
    __syncthreads();

    int warp = tid >> 5;
    int lane = tid & 31;
    int sub = lane >> 4, gl = lane & 15;
    int slot = warp * 2 + sub;
    int node = blockIdx.x * 16 + slot;
    bool valid = node < N;
    int base = 0, deg = 0;
    if (valid) { base = g_rowptr[node]; deg = g_rowptr[node + 1] - base; }

    int hh = gl >> 1;  // head owning this lane's 4 channels (C=8)
    float adh = valid ? g_al1d[node * 8 + hh] : 0.f;

    float ax = 0.f, ay = 0.f, az = 0.f, aw = 0.f, denom = 0.f;
#pragma unroll 8
    for (int j = 0; j < deg; j++) {
        int sid = __ldg(&g_adj[base + j]);
        float a = __ldg(&g_al1s[sid * 8 + hh]) + adh;
        a = a > 0.f ? a : 0.2f * a;
        float w = __expf(a);
        denom += w;
        unsigned int u = __ldg(reinterpret_cast<const unsigned int*>(&g_h1f8[sid * 64 + 4 * gl]));
        float2 f01 = fp8x2_to_f2((unsigned short)(u & 0xFFFFu));
        float2 f23 = fp8x2_to_f2((unsigned short)(u >> 16));
        ax = fmaf(f01.x, w, ax);
        ay = fmaf(f01.y, w, ay);
        az = fmaf(f23.x, w, az);
        aw = fmaf(f23.y, w, aw);
    }
    __syncwarp();
    float inv = 1.f / (denom + 1e-16f);
    float4 b4 = __ldg(reinterpret_cast<const float4*>(b1) + gl);
    float o0 = fmaf(ax, inv, b4.x);
    float o1 = fmaf(ay, inv, b4.y);
    float o2 = fmaf(az, inv, b4.z);
    float o3 = fmaf(aw, inv, b4.w);
    o0 = o0 > 0.f ? o0 : (expf(o0) - 1.f);  // elu
    o1 = o1 > 0.f ? o1 : (expf(o1) - 1.f);
    o2 = o2 > 0.f ? o2 : (expf(o2) - 1.f);
    o3 = o3 > 0.f ? o3 : (expf(o3) - 1.f);
    *reinterpret_cast<float4*>(&smh1[slot][4 * gl]) = make_float4(o0, o1, o2, o3);
    __syncwarp();

    // gemm2 for this node: lane computes h2 channels j0=2*gl, j0+1
    int j0 = 2 * gl;
    float c0 = 0.f, c1 = 0.f;
    const float4* hrow = reinterpret_cast<const float4*>(smh1[slot]);
#pragma unroll
    for (int kq = 0; kq < 16; kq++) {
        float4 h = hrow[kq];
        float2 w0 = *reinterpret_cast<const float2*>(&W2s[(4 * kq + 0) * 32 + j0]);
        float2 w1 = *reinterpret_cast<const float2*>(&W2s[(4 * kq + 1) * 32 + j0]);
        float2 w2 = *reinterpret_cast<const float2*>(&W2s[(4 * kq + 2) * 32 + j0]);
        float2 w3 = *reinterpret_cast<const float2*>(&W2s[(4 * kq + 3) * 32 + j0]);
        c0 = fmaf(h.x, w0.x, c0); c1 = fmaf(h.x, w0.y, c1);
        c0 = fmaf(h.y, w1.x, c0); c1 = fmaf(h.y, w1.y, c1);
        c0 = fmaf(h.z, w2.x, c0); c1 = fmaf(h.z, w2.y, c1);
        c0 = fmaf(h.w, w3.x, c0); c1 = fmaf(h.w, w3.y, c1);
    }
    if (valid)
        *reinterpret_cast<unsigned short*>(&g_h2f8[node * 32 + j0]) = f2_to_fp8x2(c0, c1);
    float ps = c0 * a2sS[j0] + c1 * a2sS[j0 + 1];
    float pd = c0 * a2dS[j0] + c1 * a2dS[j0 + 1];
    ps += __shfl_xor_sync(0xffffffffu, ps, 1);
    pd += __shfl_xor_sync(0xffffffffu, pd, 1);
    if (valid && (gl & 1) == 0) {
        int head = gl >> 1;
        g_al2s[node * 8 + head] = ps;
        g_al2d[node * 8 + head] = pd;
    }
}

// ---------------- fold MHA(v-path)+out_proj+fc into one 16x32 matrix ----------------
__global__ void k_prep(const float* __restrict__ in_w, const float* __restrict__ in_b,
                       const float* __restrict__ ow, const float* __restrict__ ob,
                       const float* __restrict__ fw, const float* __restrict__ fb) {
    __shared__ float T[32 * 32];
    __shared__ float u[32];
    int tid = threadIdx.x;  // 1024
    {
        int r = tid >> 5, j = tid & 31;
        float acc = 0.f;
        for (int p = 0; p < 32; p++) acc = fmaf(ow[r * 32 + p], in_w[(64 + p) * 32 + j], acc);
        T[r * 32 + j] = acc;
    }
    if (tid < 32) {
        float acc = ob[tid];
        for (int p = 0; p < 32; p++) acc = fmaf(ow[tid * 32 + p], in_b[64 + p], acc);
        u[tid] = acc;
    }
    __syncthreads();
    if (tid < 512) {
        int i = tid >> 5, j = tid & 31;
        float acc = 0.f;
        for (int r = 0; r < 32; r++) acc = fmaf(fw[i * 32 + r], T[r * 32 + j], acc);
        g_Mf[i * 32 + j] = acc;
    }
    if (tid < 16) {
        float acc = fb[tid];
        for (int r = 0; r < 32; r++) acc = fmaf(fw[tid * 32 + r], u[r], acc);
        g_cf[tid] = acc;
    }
}

// ------ agg layer 2 (fp8 gathers) FUSED with logits + log_softmax ------
// 8 lanes per node; per lane 4 channels of h2 (fp8).
__global__ __launch_bounds__(256) void k_agg2(const float* __restrict__ b2,
                                              float* __restrict__ out, int N) {
    __shared__ float MfT[32 * 16];   // 2KB, [k][i] (transposed g_Mf)
    __shared__ float cfs[16];
    __shared__ float smh2[32][32];   // 4KB
    int tid = threadIdx.x;  // 256
    for (int idx = tid; idx < 512; idx += 256) {
        int k = idx >> 4, i = idx & 15;
        MfT[idx] = g_Mf[i * 32 + k];
    }
    if (tid < 16) cfs[tid] = g_cf[tid];
    __syncthreads();

    int warp = tid >> 5;
    int lane = tid & 31;
    int sub = lane >> 3, gl = lane & 7;
    int slot = warp * 4 + sub;
    int node = blockIdx.x * 32 + slot;
    bool valid = node < N;
    int base = 0, deg = 0;
    if (valid) { base = g_rowptr[node]; deg = g_rowptr[node + 1] - base; }

    int hh = gl;  // C=4: head = gl
    float adh = valid ? g_al2d[node * 8 + hh] : 0.f;

    float ax = 0.f, ay = 0.f, az = 0.f, aw = 0.f, denom = 0.f;
#pragma unroll 8
    for (int j = 0; j < deg; j++) {
        int sid = __ldg(&g_adj[base + j]);
        float a = __ldg(&g_al2s[sid * 8 + hh]) + adh;
        a = a > 0.f ? a : 0.2f * a;
        float w = __expf(a);
        denom += w;
        unsigned int u = __ldg(reinterpret_cast<const unsigned int*>(&g_h2f8[sid * 32 + 4 * gl]));
        float2 f01 = fp8x2_to_f2((unsigned short)(u & 0xFFFFu));
        float2 f23 = fp8x2_to_f2((unsigned short)(u >> 16));
        ax = fmaf(f01.x, w, ax);
        ay = fmaf(f01.y, w, ay);
        az = fmaf(f23.x, w, az);
        aw = fmaf(f23.y, w, aw);
    }
    __syncwarp();
    float inv = 1.f / (denom + 1e-16f);
    float4 b4 = __ldg(reinterpret_cast<const float4*>(b2) + gl);
    float o0 = fmaf(ax, inv, b4.x);
    float o1 = fmaf(ay, inv, b4.y);
    float o2 = fmaf(az, inv, b4.z);
    float o3 = fmaf(aw, inv, b4.w);
    o0 = o0 > 0.f ? o0 : (expf(o0) - 1.f);  // elu
    o1 = o1 > 0.f ? o1 : (expf(o1) - 1.f);
    o2 = o2 > 0.f ? o2 : (expf(o2) - 1.f);
    o3 = o3 > 0.f ? o3 : (expf(o3) - 1.f);
    *reinterpret_cast<float4*>(&smh2[slot][4 * gl]) = make_float4(o0, o1, o2, o3);
    __syncwarp();

    // logits i0=2*gl, i0+1
    int i0 = 2 * gl;
    float l0 = cfs[i0], l1 = cfs[i0 + 1];
    const float4* hrow = reinterpret_cast<const float4*>(smh2[slot]);
#pragma unroll
    for (int kq = 0; kq < 8; kq++) {
        float4 h = hrow[kq];
        float2 m0 = *reinterpret_cast<const float2*>(&MfT[(4 * kq + 0) * 16 + i0]);
        float2 m1 = *reinterpret_cast<const float2*>(&MfT[(4 * kq + 1) * 16 + i0]);
        float2 m2 = *reinterpret_cast<const float2*>(&MfT[(4 * kq + 2) * 16 + i0]);
        float2 m3 = *reinterpret_cast<const float2*>(&MfT[(4 * kq + 3) * 16 + i0]);
        l0 = fmaf(h.x, m0.x, l0); l1 = fmaf(h.x, m0.y, l1);
        l0 = fmaf(h.y, m1.x, l0); l1 = fmaf(h.y, m1.y, l1);
        l0 = fmaf(h.z, m2.x, l0); l1 = fmaf(h.z, m2.y, l1);
        l0 = fmaf(h.w, m3.x, l0); l1 = fmaf(h.w, m3.y, l1);
    }
    float m = fmaxf(l0, l1);
#pragma unroll
    for (int o = 1; o < 8; o <<= 1) m = fmaxf(m, __shfl_xor_sync(0xffffffffu, m, o));
    float se = expf(l0 - m) + expf(l1 - m);
#pragma unroll
    for (int o = 1; o < 8; o <<= 1) se += __shfl_xor_sync(0xffffffffu, se, o);
    float lse = m + logf(se);
    if (valid)
        *reinterpret_cast<float2*>(&out[node * 16 + i0]) = make_float2(l0 - lse, l1 - lse);
}

// ---------------- launcher: forked graph (CSR chain || gemm1+prep) ----------------
extern "C" void kernel_launch(void* const* d_in, const int* in_sizes, int n_in,
                              void* d_out, int out_size) {
    const float* x = (const float*)d_in[0];
    const void* ei = d_in[1];
    const float* W1 = (const float*)d_in[2];
    const float* a1s = (const float*)d_in[3];
    const float* a1d = (const float*)d_in[4];
    const float* b1 = (const float*)d_in[5];
    const float* W2 = (const float*)d_in[6];
    const float* a2s = (const float*)d_in[7];
    const float* a2d = (const float*)d_in[8];
    const float* b2 = (const float*)d_in[9];
    const float* ipw = (const float*)d_in[10];
    const float* ipb = (const float*)d_in[11];
    const float* opw = (const float*)d_in[12];
    const float* opb = (const float*)d_in[13];
    const float* fw = (const float*)d_in[14];
    const float* fb = (const float*)d_in[15];

    int N = in_sizes[0] / 128;
    int E = in_sizes[1] / 2;
    int nb = (N + 1023) / 1024;

    cudaStream_t s2;
    cudaStreamCreateWithFlags(&s2, cudaStreamNonBlocking);
    cudaEvent_t e0, e1;
    cudaEventCreateWithFlags(&e0, cudaEventDisableTiming);
    cudaEventCreateWithFlags(&e1, cudaEventDisableTiming);

    // fork: side branch runs gemm1 + prep (independent of edge data)
    cudaEventRecord(e0, 0);
    cudaStreamWaitEvent(s2, e0, 0);
    k_gemm1<<<(N + 63) / 64, 256, 0, s2>>>(x, W1, a1s, a1d, N);
    k_prep<<<1, 1024, 0, s2>>>(ipw, ipb, opw, opb, fw, fb);
    cudaEventRecord(e1, s2);

    // main branch: CSR build by dst
    k_zero<<<(N + 255) / 256, 256>>>((const unsigned long long*)ei, N, E);
    k_count<<<(E + 255) / 256, 256>>>(ei, E);
    k_blocksum<<<nb, 1024>>>(N);
    k_scan<<<nb, 1024>>>(N, nb);
    k_scatter<<<(E + N + 255) / 256, 256>>>(ei, E, N);

    // join, then the two fused aggregation layers
    cudaStreamWaitEvent(0, e1, 0);
    k_agg1<<<(N + 15) / 16, 256>>>(b1, W2, a2s, a2d, N);
    k_agg2<<<(N + 31) / 32, 256>>>(b2, (float*)d_out, N);

    cudaStreamDestroy(s2);
    cudaEventDestroy(e0);
    cudaEventDestroy(e1);
}

// round 15
// speedup vs baseline: 1.1609x; 1.0238x over previous
#include <cuda_runtime.h>
#include <cuda_fp16.h>
#include <cuda_fp8.h>

#define MAXN 50000
#define MAXE 1600000

// ---------------- scratch (static device allocations) ----------------
__device__ int   g_is64;
__device__ int   g_cnt[MAXN];
__device__ int   g_rowptr[MAXN + 1];
__device__ int   g_cursor[MAXN];
__device__ int   g_adj[MAXE + MAXN];
__device__ __align__(16) unsigned char g_h1f8[MAXN * 64];  // layer-1 features, fp8 e4m3
__device__ __align__(16) unsigned char g_h2f8[MAXN * 32];  // layer-2 features, fp8 e4m3
__device__ float g_al1s[MAXN * 8], g_al1d[MAXN * 8];
__device__ float g_al2s[MAXN * 8], g_al2d[MAXN * 8];
__device__ float g_Mf[16 * 32];
__device__ float g_cf[16];

// fp8x2 helpers
__device__ __forceinline__ unsigned short f2_to_fp8x2(float a, float b) {
    return (unsigned short)__nv_cvt_float2_to_fp8x2(make_float2(a, b), __NV_SATFINITE, __NV_E4M3);
}
__device__ __forceinline__ float2 fp8x2_to_f2(unsigned short v) {
    __half2_raw h = __nv_cvt_fp8x2_to_halfraw2((__nv_fp8x2_storage_t)v, __NV_E4M3);
    return __half22float2(*reinterpret_cast<__half2*>(&h));
}

// read edge value i (src row: i in [0,E); dst row: i in [E,2E))
__device__ __forceinline__ int edge_val(const void* ei, long long idx) {
    return g_is64 ? (int)((const long long*)ei)[idx] : ((const int*)ei)[idx];
}

// ---------------- dtype probe + CSR build ----------------
__global__ void k_zero(const unsigned long long* __restrict__ w, int N, int E) {
    int i = blockIdx.x * blockDim.x + threadIdx.x;
    if (i < N) g_cnt[i] = 0;
    if (i == 0) g_is64 = 1;  // optimistic; cleared below if int32
    int n = E < 2048 ? E : 2048;
    if (i < n && (w[i] >> 32) != 0ull) g_is64 = 0;  // high half set => int32 pairs
}

__global__ void k_count(const void* __restrict__ ei, int E) {
    int i = blockIdx.x * blockDim.x + threadIdx.x;
    if (i < E) {
        int d = edge_val(ei, (long long)E + i);
        atomicAdd(&g_cnt[d], 1);
    }
}

// block-level inclusive scan; block offset computed in-kernel by strided sum of
// all preceding g_cnt entries (removes the separate blocksum kernel).
__global__ void k_scan(int N) {
    __shared__ int sh[1024];
    int tid = threadIdx.x;
    int blockStart = blockIdx.x * 1024;
    // offset = sum of (g_cnt[i]+1) for i < blockStart
    int part = 0;
    for (int i = tid; i < blockStart; i += 1024) part += g_cnt[i] + 1;
    sh[tid] = part;
    __syncthreads();
    for (int o = 512; o > 0; o >>= 1) {
        if (tid < o) sh[tid] += sh[tid + o];
        __syncthreads();
    }
    int soff = sh[0];
    __syncthreads();
    // inclusive scan of this block's chunk
    int i = blockStart + tid;
    int v = (i < N) ? (g_cnt[i] + 1) : 0;  // +1 = self loop
    sh[tid] = v;
    __syncthreads();
    for (int o = 1; o < 1024; o <<= 1) {
        int t = 0;
        if (tid >= (unsigned)o) t = sh[tid - o];
        __syncthreads();
        sh[tid] += t;
        __syncthreads();
    }
    if (i < N) {
        int incl = sh[tid] + soff;
        g_rowptr[i + 1] = incl;
        g_cursor[i] = incl - v;
        if (i == 0) g_rowptr[0] = 0;
    }
}

__global__ void k_scatter(const void* __restrict__ ei, int E, int N) {
    int i = blockIdx.x * blockDim.x + threadIdx.x;
    if (i < E) {
        int d = edge_val(ei, (long long)E + i);
        int s = edge_val(ei, i);
        int pos = atomicAdd(&g_cursor[d], 1);
        g_adj[pos] = s;
    } else if (i < E + N) {  // self loops
        int n = i - E;
        int pos = atomicAdd(&g_cursor[n], 1);
        g_adj[pos] = n;
    }
}

// ------ GEMM layer 1: 4 channels x 4 nodes register tile ------
// Fused: fp8 feature-table pack + attention logits.
__global__ __launch_bounds__(256) void k_gemm1(const float* __restrict__ X,
                                               const float* __restrict__ W,
                                               const float* __restrict__ a_src,
                                               const float* __restrict__ a_dst, int N) {
    constexpr int FIN = 128, TX = 16, NN = 4, NPB = 64;
    __shared__ float4 Ws4[FIN * TX];  // W as [FIN][TX] float4
    int tid = threadIdx.x;
    int tx = tid % TX, ty = tid / TX;
    const float4* W4 = reinterpret_cast<const float4*>(W);
    for (int idx = tid; idx < FIN * TX; idx += 256) Ws4[idx] = W4[idx];
    float4 as4 = __ldg(reinterpret_cast<const float4*>(a_src) + tx);
    float4 ad4 = __ldg(reinterpret_cast<const float4*>(a_dst) + tx);
    __syncthreads();

    const float4* X4 = reinterpret_cast<const float4*>(X);
    int n0 = blockIdx.x * NPB + ty * NN;
    bool v[NN];
#pragma unroll
    for (int nn = 0; nn < NN; nn++) v[nn] = (n0 + nn) < N;

    float acc[NN][4];
#pragma unroll
    for (int nn = 0; nn < NN; nn++)
        acc[nn][0] = acc[nn][1] = acc[nn][2] = acc[nn][3] = 0.f;

#pragma unroll 2
    for (int kq = 0; kq < FIN / 4; kq++) {
        float4 w0 = Ws4[(4 * kq + 0) * TX + tx];
        float4 w1 = Ws4[(4 * kq + 1) * TX + tx];
        float4 w2 = Ws4[(4 * kq + 2) * TX + tx];
        float4 w3 = Ws4[(4 * kq + 3) * TX + tx];
#pragma unroll
        for (int nn = 0; nn < NN; nn++) {
            float4 xv = v[nn] ? __ldg(&X4[(n0 + nn) * (FIN / 4) + kq])
                              : make_float4(0.f, 0.f, 0.f, 0.f);
            acc[nn][0] = fmaf(xv.x, w0.x, acc[nn][0]);
            acc[nn][1] = fmaf(xv.x, w0.y, acc[nn][1]);
            acc[nn][2] = fmaf(xv.x, w0.z, acc[nn][2]);
            acc[nn][3] = fmaf(xv.x, w0.w, acc[nn][3]);
            acc[nn][0] = fmaf(xv.y, w1.x, acc[nn][0]);
            acc[nn][1] = fmaf(xv.y, w1.y, acc[nn][1]);
            acc[nn][2] = fmaf(xv.y, w1.z, acc[nn][2]);
            acc[nn][3] = fmaf(xv.y, w1.w, acc[nn][3]);
            acc[nn][0] = fmaf(xv.z, w2.x, acc[nn][0]);
            acc[nn][1] = fmaf(xv.z, w2.y, acc[nn][1]);
            acc[nn][2] = fmaf(xv.z, w2.z, acc[nn][2]);
            acc[nn][3] = fmaf(xv.z, w2.w, acc[nn][3]);
            acc[nn][0] = fmaf(xv.w, w3.x, acc[nn][0]);
            acc[nn][1] = fmaf(xv.w, w3.y, acc[nn][1]);
            acc[nn][2] = fmaf(xv.w, w3.z, acc[nn][2]);
            acc[nn][3] = fmaf(xv.w, w3.w, acc[nn][3]);
        }
    }

#pragma unroll
    for (int nn = 0; nn < NN; nn++) {
        int n = n0 + nn;
        if (v[nn]) {  // fp8 pack: this thread's 4 contiguous channels
            unsigned int p = (unsigned int)f2_to_fp8x2(acc[nn][0], acc[nn][1]) |
                             ((unsigned int)f2_to_fp8x2(acc[nn][2], acc[nn][3]) << 16);
            *reinterpret_cast<unsigned int*>(&g_h1f8[n * 64 + 4 * tx]) = p;
        }
        float ps = acc[nn][0] * as4.x + acc[nn][1] * as4.y +
                   acc[nn][2] * as4.z + acc[nn][3] * as4.w;
        float pd = acc[nn][0] * ad4.x + acc[nn][1] * ad4.y +
                   acc[nn][2] * ad4.z + acc[nn][3] * ad4.w;
        ps += __shfl_xor_sync(0xffffffffu, ps, 1);
        pd += __shfl_xor_sync(0xffffffffu, pd, 1);
        if (v[nn] && (tx & 1) == 0) {
            int head = tx >> 1;
            g_al1s[n * 8 + head] = ps;
            g_al1d[n * 8 + head] = pd;
        }
    }
}

// ------ agg layer 1 (single-pass softmax, fp8 gathers) FUSED gemm2 + layer-2 logits ------
// 16 lanes per node; per lane 4 channels of h1 (fp8).
__global__ __launch_bounds__(256) void k_agg1(const float* __restrict__ b1,
                                              const float* __restrict__ W2,
                                              const float* __restrict__ a2s,
                                              const float* __restrict__ a2d, int N) {
    __shared__ float W2s[64 * 32];     // 8KB, [k][j] row-major
    __shared__ float smh1[16][64];     // 4KB, staged h1 per node slot
    __shared__ float a2sS[32], a2dS[32];
    int tid = threadIdx.x;
    for (int idx = tid; idx < 64 * 32; idx += 256) W2s[idx] = W2[idx];
    if (tid < 32) { a2sS[tid] = a2s[tid]; a2dS[tid] = a2d[tid]; }
    __syncthreads();

    int warp = tid >> 5;
    int lane = tid & 31;
    int sub = lane >> 4, gl = lane & 15;
    int slot = warp * 2 + sub;
    int node = blockIdx.x * 16 + slot;
    bool valid = node < N;
    int base = 0, deg = 0;
    if (valid) { base = g_rowptr[node]; deg = g_rowptr[node + 1] - base; }

    int hh = gl >> 1;  // head owning this lane's 4 channels (C=8)
    float adh = valid ? g_al1d[node * 8 + hh] : 0.f;

    float ax = 0.f, ay = 0.f, az = 0.f, aw = 0.f, denom = 0.f;
#pragma unroll 4
    for (int j = 0; j < deg; j++) {
        int sid = __ldg(&g_adj[base + j]);
        float a = __ldg(&g_al1s[sid * 8 + hh]) + adh;
        a = a > 0.f ? a : 0.2f * a;
        float w = __expf(a);
        denom += w;
        unsigned int u = __ldg(reinterpret_cast<const unsigned int*>(&g_h1f8[sid * 64 + 4 * gl]));
        float2 f01 = fp8x2_to_f2((unsigned short)(u & 0xFFFFu));
        float2 f23 = fp8x2_to_f2((unsigned short)(u >> 16));
        ax = fmaf(f01.x, w, ax);
        ay = fmaf(f01.y, w, ay);
        az = fmaf(f23.x, w, az);
        aw = fmaf(f23.y, w, aw);
    }
    __syncwarp();
    float inv = 1.f / (denom + 1e-16f);
    float4 b4 = __ldg(reinterpret_cast<const float4*>(b1) + gl);
    float o0 = fmaf(ax, inv, b4.x);
    float o1 = fmaf(ay, inv, b4.y);
    float o2 = fmaf(az, inv, b4.z);
    float o3 = fmaf(aw, inv, b4.w);
    o0 = o0 > 0.f ? o0 : (expf(o0) - 1.f);  // elu
    o1 = o1 > 0.f ? o1 : (expf(o1) - 1.f);
    o2 = o2 > 0.f ? o2 : (expf(o2) - 1.f);
    o3 = o3 > 0.f ? o3 : (expf(o3) - 1.f);
    *reinterpret_cast<float4*>(&smh1[slot][4 * gl]) = make_float4(o0, o1, o2, o3);
    __syncwarp();

    // gemm2 for this node: lane computes h2 channels j0=2*gl, j0+1
    int j0 = 2 * gl;
    float c0 = 0.f, c1 = 0.f;
    const float4* hrow = reinterpret_cast<const float4*>(smh1[slot]);
#pragma unroll
    for (int kq = 0; kq < 16; kq++) {
        float4 h = hrow[kq];
        float2 w0 = *reinterpret_cast<const float2*>(&W2s[(4 * kq + 0) * 32 + j0]);
        float2 w1 = *reinterpret_cast<const float2*>(&W2s[(4 * kq + 1) * 32 + j0]);
        float2 w2 = *reinterpret_cast<const float2*>(&W2s[(4 * kq + 2) * 32 + j0]);
        float2 w3 = *reinterpret_cast<const float2*>(&W2s[(4 * kq + 3) * 32 + j0]);
        c0 = fmaf(h.x, w0.x, c0); c1 = fmaf(h.x, w0.y, c1);
        c0 = fmaf(h.y, w1.x, c0); c1 = fmaf(h.y, w1.y, c1);
        c0 = fmaf(h.z, w2.x, c0); c1 = fmaf(h.z, w2.y, c1);
        c0 = fmaf(h.w, w3.x, c0); c1 = fmaf(h.w, w3.y, c1);
    }
    if (valid)
        *reinterpret_cast<unsigned short*>(&g_h2f8[node * 32 + j0]) = f2_to_fp8x2(c0, c1);
    float ps = c0 * a2sS[j0] + c1 * a2sS[j0 + 1];
    float pd = c0 * a2dS[j0] + c1 * a2dS[j0 + 1];
    ps += __shfl_xor_sync(0xffffffffu, ps, 1);
    pd += __shfl_xor_sync(0xffffffffu, pd, 1);
    if (valid && (gl & 1) == 0) {
        int head = gl >> 1;
        g_al2s[node * 8 + head] = ps;
        g_al2d[node * 8 + head] = pd;
    }
}

// ---------------- fold MHA(v-path)+out_proj+fc into one 16x32 matrix ----------------
__global__ void k_prep(const float* __restrict__ in_w, const float* __restrict__ in_b,
                       const float* __restrict__ ow, const float* __restrict__ ob,
                       const float* __restrict__ fw, const float* __restrict__ fb) {
    __shared__ float T[32 * 32];
    __shared__ float u[32];
    int tid = threadIdx.x;  // 1024
    {
        int r = tid >> 5, j = tid & 31;
        float acc = 0.f;
        for (int p = 0; p < 32; p++) acc = fmaf(ow[r * 32 + p], in_w[(64 + p) * 32 + j], acc);
        T[r * 32 + j] = acc;
    }
    if (tid < 32) {
        float acc = ob[tid];
        for (int p = 0; p < 32; p++) acc = fmaf(ow[tid * 32 + p], in_b[64 + p], acc);
        u[tid] = acc;
    }
    __syncthreads();
    if (tid < 512) {
        int i = tid >> 5, j = tid & 31;
        float acc = 0.f;
        for (int r = 0; r < 32; r++) acc = fmaf(fw[i * 32 + r], T[r * 32 + j], acc);
        g_Mf[i * 32 + j] = acc;
    }
    if (tid < 16) {
        float acc = fb[tid];
        for (int r = 0; r < 32; r++) acc = fmaf(fw[tid * 32 + r], u[r], acc);
        g_cf[tid] = acc;
    }
}

// ------ agg layer 2 (fp8 gathers) FUSED with logits + log_softmax ------
// 8 lanes per node; per lane 4 channels of h2 (fp8).
__global__ __launch_bounds__(256) void k_agg2(const float* __restrict__ b2,
                                              float* __restrict__ out, int N) {
    __shared__ float MfT[32 * 16];   // 2KB, [k][i] (transposed g_Mf)
    __shared__ float cfs[16];
    __shared__ float smh2[32][32];   // 4KB
    int tid = threadIdx.x;  // 256
    for (int idx = tid; idx < 512; idx += 256) {
        int k = idx >> 4, i = idx & 15;
        MfT[idx] = g_Mf[i * 32 + k];
    }
    if (tid < 16) cfs[tid] = g_cf[tid];
    __syncthreads();

    int warp = tid >> 5;
    int lane = tid & 31;
    int sub = lane >> 3, gl = lane & 7;
    int slot = warp * 4 + sub;
    int node = blockIdx.x * 32 + slot;
    bool valid = node < N;
    int base = 0, deg = 0;
    if (valid) { base = g_rowptr[node]; deg = g_rowptr[node + 1] - base; }

    int hh = gl;  // C=4: head = gl
    float adh = valid ? g_al2d[node * 8 + hh] : 0.f;

    float ax = 0.f, ay = 0.f, az = 0.f, aw = 0.f, denom = 0.f;
#pragma unroll 4
    for (int j = 0; j < deg; j++) {
        int sid = __ldg(&g_adj[base + j]);
        float a = __ldg(&g_al2s[sid * 8 + hh]) + adh;
        a = a > 0.f ? a : 0.2f * a;
        float w = __expf(a);
        denom += w;
        unsigned int u = __ldg(reinterpret_cast<const unsigned int*>(&g_h2f8[sid * 32 + 4 * gl]));
        float2 f01 = fp8x2_to_f2((unsigned short)(u & 0xFFFFu));
        float2 f23 = fp8x2_to_f2((unsigned short)(u >> 16));
        ax = fmaf(f01.x, w, ax);
        ay = fmaf(f01.y, w, ay);
        az = fmaf(f23.x, w, az);
        aw = fmaf(f23.y, w, aw);
    }
    __syncwarp();
    float inv = 1.f / (denom + 1e-16f);
    float4 b4 = __ldg(reinterpret_cast<const float4*>(b2) + gl);
    float o0 = fmaf(ax, inv, b4.x);
    float o1 = fmaf(ay, inv, b4.y);
    float o2 = fmaf(az, inv, b4.z);
    float o3 = fmaf(aw, inv, b4.w);
    o0 = o0 > 0.f ? o0 : (expf(o0) - 1.f);  // elu
    o1 = o1 > 0.f ? o1 : (expf(o1) - 1.f);
    o2 = o2 > 0.f ? o2 : (expf(o2) - 1.f);
    o3 = o3 > 0.f ? o3 : (expf(o3) - 1.f);
    *reinterpret_cast<float4*>(&smh2[slot][4 * gl]) = make_float4(o0, o1, o2, o3);
    __syncwarp();

    // logits i0=2*gl, i0+1
    int i0 = 2 * gl;
    float l0 = cfs[i0], l1 = cfs[i0 + 1];
    const float4* hrow = reinterpret_cast<const float4*>(smh2[slot]);
#pragma unroll
    for (int kq = 0; kq < 8; kq++) {
        float4 h = hrow[kq];
        float2 m0 = *reinterpret_cast<const float2*>(&MfT[(4 * kq + 0) * 16 + i0]);
        float2 m1 = *reinterpret_cast<const float2*>(&MfT[(4 * kq + 1) * 16 + i0]);
        float2 m2 = *reinterpret_cast<const float2*>(&MfT[(4 * kq + 2) * 16 + i0]);
        float2 m3 = *reinterpret_cast<const float2*>(&MfT[(4 * kq + 3) * 16 + i0]);
        l0 = fmaf(h.x, m0.x, l0); l1 = fmaf(h.x, m0.y, l1);
        l0 = fmaf(h.y, m1.x, l0); l1 = fmaf(h.y, m1.y, l1);
        l0 = fmaf(h.z, m2.x, l0); l1 = fmaf(h.z, m2.y, l1);
        l0 = fmaf(h.w, m3.x, l0); l1 = fmaf(h.w, m3.y, l1);
    }
    float m = fmaxf(l0, l1);
#pragma unroll
    for (int o = 1; o < 8; o <<= 1) m = fmaxf(m, __shfl_xor_sync(0xffffffffu, m, o));
    float se = expf(l0 - m) + expf(l1 - m);
#pragma unroll
    for (int o = 1; o < 8; o <<= 1) se += __shfl_xor_sync(0xffffffffu, se, o);
    float lse = m + logf(se);
    if (valid)
        *reinterpret_cast<float2*>(&out[node * 16 + i0]) = make_float2(l0 - lse, l1 - lse);
}

// ---------------- launcher: forked graph (CSR chain || gemm1+prep) ----------------
extern "C" void kernel_launch(void* const* d_in, const int* in_sizes, int n_in,
                              void* d_out, int out_size) {
    const float* x = (const float*)d_in[0];
    const void* ei = d_in[1];
    const float* W1 = (const float*)d_in[2];
    const float* a1s = (const float*)d_in[3];
    const float* a1d = (const float*)d_in[4];
    const float* b1 = (const float*)d_in[5];
    const float* W2 = (const float*)d_in[6];
    const float* a2s = (const float*)d_in[7];
    const float* a2d = (const float*)d_in[8];
    const float* b2 = (const float*)d_in[9];
    const float* ipw = (const float*)d_in[10];
    const float* ipb = (const float*)d_in[11];
    const float* opw = (const float*)d_in[12];
    const float* opb = (const float*)d_in[13];
    const float* fw = (const float*)d_in[14];
    const float* fb = (const float*)d_in[15];

    int N = in_sizes[0] / 128;
    int E = in_sizes[1] / 2;
    int nb = (N + 1023) / 1024;

    cudaStream_t s2;
    cudaStreamCreateWithFlags(&s2, cudaStreamNonBlocking);
    cudaEvent_t e0, e1;
    cudaEventCreateWithFlags(&e0, cudaEventDisableTiming);
    cudaEventCreateWithFlags(&e1, cudaEventDisableTiming);

    // fork: side branch runs gemm1 + prep (independent of edge data)
    cudaEventRecord(e0, 0);
    cudaStreamWaitEvent(s2, e0, 0);
    k_gemm1<<<(N + 63) / 64, 256, 0, s2>>>(x, W1, a1s, a1d, N);
    k_prep<<<1, 1024, 0, s2>>>(ipw, ipb, opw, opb, fw, fb);
    cudaEventRecord(e1, s2);

    // main branch: CSR build by dst
    k_zero<<<(N + 255) / 256, 256>>>((const unsigned long long*)ei, N, E);
    k_count<<<(E + 255) / 256, 256>>>(ei, E);
    k_scan<<<nb, 1024>>>(N);
    k_scatter<<<(E + N + 255) / 256, 256>>>(ei, E, N);

    // join, then the two fused aggregation layers
    cudaStreamWaitEvent(0, e1, 0);
    k_agg1<<<(N + 15) / 16, 256>>>(b1, W2, a2s, a2d, N);
    k_agg2<<<(N + 31) / 32, 256>>>(b2, (float*)d_out, N);

    cudaStreamDestroy(s2);
    cudaEventDestroy(e0);
    cudaEventDestroy(e1);
}